// round 2
// baseline (speedup 1.0000x reference)
#include <cuda_runtime.h>
#include <math.h>

#define NB 8
#define NT 2048
#define NE 1024
#define NH 64

// Scratch for projected Q, K, V: [B, T, H] fp32 each (4 MB each).
__device__ float g_Q[NB * NT * NH];
__device__ float g_K[NB * NT * NH];
__device__ float g_V[NB * NT * NH];

// ---------------------------------------------------------------------------
// Kernel 1: fused QKV projection.
//   O[row, h] = sum_e x[row, e] * W[e, h],  W is [E, H] row-major.
// Grid: (256 row-tiles of 64, 3 matrices). Block: 256 threads (16x16),
// each thread computes a 4x4 micro-tile of a 64x64 output tile.
// k-tile depth 32. X tile stored k-major in smem with an XOR swizzle so both
// the transpose stores and the compute-loop float4 loads are conflict-free.
// ---------------------------------------------------------------------------
__global__ __launch_bounds__(256) void qkv_kernel(
    const float* __restrict__ x,
    const float* __restrict__ Wq,
    const float* __restrict__ Wk,
    const float* __restrict__ Wv)
{
    const float* W = (blockIdx.y == 0) ? Wq : (blockIdx.y == 1 ? Wk : Wv);
    float*       O = (blockIdx.y == 0) ? g_Q : (blockIdx.y == 1 ? g_K : g_V);

    __shared__ float Xs[32 * 64];   // element (k, r) at Xs[k*64 + (r ^ ((k&15)<<2))]
    __shared__ float Ws2[32 * 64];  // element (k, h) at Ws2[k*64 + h]

    const int tid  = threadIdx.x;
    const int tx   = tid & 15;       // output col group
    const int ty   = tid >> 4;       // output row group
    const int row0 = blockIdx.x * 64;

    const int lr = tid >> 3;         // 0..31 : X row pair base
    const int lc = (tid & 7) * 4;    // 0..28 : first k of float4

    float acc[4][4] = {};

    for (int k0 = 0; k0 < NE; k0 += 32) {
        // Load X tile [64 rows x 32 k], transpose+swizzle into smem.
        #pragma unroll
        for (int half = 0; half < 2; ++half) {
            int r = lr + half * 32;
            float4 xv = *(const float4*)(x + (size_t)(row0 + r) * NE + k0 + lc);
            Xs[(lc + 0) * 64 + (r ^ (((lc + 0) & 15) << 2))] = xv.x;
            Xs[(lc + 1) * 64 + (r ^ (((lc + 1) & 15) << 2))] = xv.y;
            Xs[(lc + 2) * 64 + (r ^ (((lc + 2) & 15) << 2))] = xv.z;
            Xs[(lc + 3) * 64 + (r ^ (((lc + 3) & 15) << 2))] = xv.w;
        }
        // Load W tile [32 k x 64 h] directly (row-major, coalesced).
        #pragma unroll
        for (int half = 0; half < 2; ++half) {
            int kk = ty + half * 16;
            *(float4*)&Ws2[kk * 64 + tx * 4] =
                *(const float4*)(W + (size_t)(k0 + kk) * NH + tx * 4);
        }
        __syncthreads();

        #pragma unroll
        for (int kk = 0; kk < 32; ++kk) {
            float4 a = *(const float4*)&Xs[kk * 64 + ((ty * 4) ^ ((kk & 15) << 2))];
            float4 b = *(const float4*)&Ws2[kk * 64 + tx * 4];
            acc[0][0] = fmaf(a.x, b.x, acc[0][0]); acc[0][1] = fmaf(a.x, b.y, acc[0][1]);
            acc[0][2] = fmaf(a.x, b.z, acc[0][2]); acc[0][3] = fmaf(a.x, b.w, acc[0][3]);
            acc[1][0] = fmaf(a.y, b.x, acc[1][0]); acc[1][1] = fmaf(a.y, b.y, acc[1][1]);
            acc[1][2] = fmaf(a.y, b.z, acc[1][2]); acc[1][3] = fmaf(a.y, b.w, acc[1][3]);
            acc[2][0] = fmaf(a.z, b.x, acc[2][0]); acc[2][1] = fmaf(a.z, b.y, acc[2][1]);
            acc[2][2] = fmaf(a.z, b.z, acc[2][2]); acc[2][3] = fmaf(a.z, b.w, acc[2][3]);
            acc[3][0] = fmaf(a.w, b.x, acc[3][0]); acc[3][1] = fmaf(a.w, b.y, acc[3][1]);
            acc[3][2] = fmaf(a.w, b.z, acc[3][2]); acc[3][3] = fmaf(a.w, b.w, acc[3][3]);
        }
        __syncthreads();
    }

    #pragma unroll
    for (int i = 0; i < 4; ++i) {
        float4 v = make_float4(acc[i][0], acc[i][1], acc[i][2], acc[i][3]);
        *(float4*)(O + (size_t)(row0 + ty * 4 + i) * NH + tx * 4) = v;
    }
}

// ---------------------------------------------------------------------------
// Kernel 2: causal flash attention, fp32, online softmax.
// Grid: (16 pair-slots, 8 batches). Block 256 threads (16x16).
// Each block handles two q-tiles: qt = 31-bx and qt = bx, so every block does
// exactly (32-bx) + (bx+1) = 33 key-tile units -> perfectly load balanced,
// 128 blocks = single wave on the chip.
// Smem: Qs (k-major swizzled), KP (K tile k-major swizzled, later aliased as
// the P tile row-major), Vs (row-major). Exactly 48 KB static.
// ---------------------------------------------------------------------------
__global__ __launch_bounds__(256) void attn_kernel(float* __restrict__ out)
{
    __shared__ float Qs[64 * 64];  // element (h, i) at Qs[h*64 + (i ^ (h & 60))]
    __shared__ float KP[64 * 64];  // K: (h, j) at KP[h*64 + (j ^ (h & 60))]; later P: (i, j) at KP[i*64 + j]
    __shared__ float Vs[64 * 64];  // element (j, h) at Vs[j*64 + h]

    const int tid = threadIdx.x;
    const int tx  = tid & 15;
    const int ty  = tid >> 4;
    const int b   = blockIdx.y;

    const float* Qb = g_Q + (size_t)b * NT * NH;
    const float* Kb = g_K + (size_t)b * NT * NH;
    const float* Vb = g_V + (size_t)b * NT * NH;
    float*       Ob = out + (size_t)b * NT * NH;

    const float scale = 0.125f;  // 1/sqrt(64)

    #pragma unroll 1
    for (int qi = 0; qi < 2; ++qi) {
        const int qt   = qi ? (int)blockIdx.x : 31 - (int)blockIdx.x;
        const int row0 = qt * 64;

        __syncthreads();  // protect Qs/KP/Vs from previous q-tile's readers
        // Load Q tile, transpose to k-major with swizzle.
        #pragma unroll
        for (int it = 0; it < 4; ++it) {
            int idx = tid + it * 256;
            int r   = idx >> 4;            // 0..63 token row
            int h0  = (idx & 15) * 4;      // 0..60 first h of float4
            float4 v = *(const float4*)(Qb + (size_t)(row0 + r) * NH + h0);
            Qs[(h0 + 0) * 64 + (r ^ h0)] = v.x;
            Qs[(h0 + 1) * 64 + (r ^ h0)] = v.y;
            Qs[(h0 + 2) * 64 + (r ^ h0)] = v.z;
            Qs[(h0 + 3) * 64 + (r ^ h0)] = v.w;
        }

        float m[4], l[4], o[4][4];
        #pragma unroll
        for (int i = 0; i < 4; ++i) {
            m[i] = -INFINITY;
            l[i] = 0.f;
            #pragma unroll
            for (int j = 0; j < 4; ++j) o[i][j] = 0.f;
        }

        #pragma unroll 1
        for (int jt = 0; jt <= qt; ++jt) {
            __syncthreads();  // previous tile's PV reads of KP/Vs done
            // Load K tile (transpose+swizzle) and V tile (direct).
            #pragma unroll
            for (int it = 0; it < 4; ++it) {
                int idx = tid + it * 256;
                int r   = idx >> 4;
                int h0  = (idx & 15) * 4;
                float4 kv = *(const float4*)(Kb + (size_t)(jt * 64 + r) * NH + h0);
                KP[(h0 + 0) * 64 + (r ^ h0)] = kv.x;
                KP[(h0 + 1) * 64 + (r ^ h0)] = kv.y;
                KP[(h0 + 2) * 64 + (r ^ h0)] = kv.z;
                KP[(h0 + 3) * 64 + (r ^ h0)] = kv.w;
                float4 vv = *(const float4*)(Vb + (size_t)(jt * 64 + r) * NH + h0);
                *(float4*)&Vs[r * 64 + h0] = vv;
            }
            __syncthreads();

            // S = Q K^T  (inner dim h = 64)
            float s[4][4] = {};
            #pragma unroll
            for (int h = 0; h < 64; ++h) {
                float4 a  = *(const float4*)&Qs[h * 64 + ((ty * 4) ^ (h & 60))];
                float4 bq = *(const float4*)&KP[h * 64 + ((tx * 4) ^ (h & 60))];
                s[0][0] = fmaf(a.x, bq.x, s[0][0]); s[0][1] = fmaf(a.x, bq.y, s[0][1]);
                s[0][2] = fmaf(a.x, bq.z, s[0][2]); s[0][3] = fmaf(a.x, bq.w, s[0][3]);
                s[1][0] = fmaf(a.y, bq.x, s[1][0]); s[1][1] = fmaf(a.y, bq.y, s[1][1]);
                s[1][2] = fmaf(a.y, bq.z, s[1][2]); s[1][3] = fmaf(a.y, bq.w, s[1][3]);
                s[2][0] = fmaf(a.z, bq.x, s[2][0]); s[2][1] = fmaf(a.z, bq.y, s[2][1]);
                s[2][2] = fmaf(a.z, bq.z, s[2][2]); s[2][3] = fmaf(a.z, bq.w, s[2][3]);
                s[3][0] = fmaf(a.w, bq.x, s[3][0]); s[3][1] = fmaf(a.w, bq.y, s[3][1]);
                s[3][2] = fmaf(a.w, bq.z, s[3][2]); s[3][3] = fmaf(a.w, bq.w, s[3][3]);
            }

            // Scale + causal mask + online softmax (all in registers).
            float alpha[4];
            const bool diag = (jt == qt);
            #pragma unroll
            for (int i = 0; i < 4; ++i) {
                const int gi = ty * 4 + i;
                #pragma unroll
                for (int j = 0; j < 4; ++j) {
                    bool masked = diag && ((tx * 4 + j) > gi);
                    s[i][j] = masked ? -INFINITY : s[i][j] * scale;
                }
                float rm = fmaxf(fmaxf(s[i][0], s[i][1]), fmaxf(s[i][2], s[i][3]));
                rm = fmaxf(rm, __shfl_xor_sync(0xffffffffu, rm, 8));
                rm = fmaxf(rm, __shfl_xor_sync(0xffffffffu, rm, 4));
                rm = fmaxf(rm, __shfl_xor_sync(0xffffffffu, rm, 2));
                rm = fmaxf(rm, __shfl_xor_sync(0xffffffffu, rm, 1));
                float nm = fmaxf(m[i], rm);
                float rs = 0.f;
                #pragma unroll
                for (int j = 0; j < 4; ++j) {
                    s[i][j] = __expf(s[i][j] - nm);
                    rs += s[i][j];
                }
                rs += __shfl_xor_sync(0xffffffffu, rs, 8);
                rs += __shfl_xor_sync(0xffffffffu, rs, 4);
                rs += __shfl_xor_sync(0xffffffffu, rs, 2);
                rs += __shfl_xor_sync(0xffffffffu, rs, 1);
                alpha[i] = __expf(m[i] - nm);
                l[i] = l[i] * alpha[i] + rs;
                m[i] = nm;
            }

            __syncthreads();  // all K reads (S gemm) done before P overwrites KP
            #pragma unroll
            for (int i = 0; i < 4; ++i) {
                float4 pv = make_float4(s[i][0], s[i][1], s[i][2], s[i][3]);
                *(float4*)&KP[(ty * 4 + i) * 64 + tx * 4] = pv;
            }
            __syncthreads();  // P visible

            // Rescale accumulators, then O += P * V  (inner dim j = 64).
            #pragma unroll
            for (int u = 0; u < 4; ++u) {
                o[u][0] *= alpha[u]; o[u][1] *= alpha[u];
                o[u][2] *= alpha[u]; o[u][3] *= alpha[u];
            }
            #pragma unroll
            for (int j4 = 0; j4 < 16; ++j4) {
                float pu[4][4];
                #pragma unroll
                for (int u = 0; u < 4; ++u)
                    *(float4*)pu[u] = *(const float4*)&KP[(ty * 4 + u) * 64 + j4 * 4];
                #pragma unroll
                for (int e = 0; e < 4; ++e) {
                    float4 bv = *(const float4*)&Vs[(j4 * 4 + e) * 64 + tx * 4];
                    #pragma unroll
                    for (int u = 0; u < 4; ++u) {
                        o[u][0] = fmaf(pu[u][e], bv.x, o[u][0]);
                        o[u][1] = fmaf(pu[u][e], bv.y, o[u][1]);
                        o[u][2] = fmaf(pu[u][e], bv.z, o[u][2]);
                        o[u][3] = fmaf(pu[u][e], bv.w, o[u][3]);
                    }
                }
            }
        }

        // Epilogue: divide by l and store.
        #pragma unroll
        for (int u = 0; u < 4; ++u) {
            float inv = 1.0f / l[u];
            float4 v = make_float4(o[u][0] * inv, o[u][1] * inv,
                                   o[u][2] * inv, o[u][3] * inv);
            *(float4*)(Ob + (size_t)(row0 + ty * 4 + u) * NH + tx * 4) = v;
        }
    }
}

extern "C" void kernel_launch(void* const* d_in, const int* in_sizes, int n_in,
                              void* d_out, int out_size)
{
    const float* x  = (const float*)d_in[0];
    const float* Wq = (const float*)d_in[1];
    const float* Wk = (const float*)d_in[2];
    const float* Wv = (const float*)d_in[3];
    float* out = (float*)d_out;

    qkv_kernel<<<dim3(256, 3), 256>>>(x, Wq, Wk, Wv);
    attn_kernel<<<dim3(16, 8), 256>>>(out);
}

// round 4
// speedup vs baseline: 1.6433x; 1.6433x over previous
#include <cuda_runtime.h>
#include <cuda_bf16.h>
#include <math.h>
#include <stdint.h>

#define NB 8
#define NT 2048
#define NE 1024
#define NH 64

// Scratch: projected Q, K, V [B, T, H] fp32 (4 MB each).
__device__ float g_Q[NB * NT * NH];
__device__ float g_K[NB * NT * NH];
__device__ float g_V[NB * NT * NH];
// W transposed+split to bf16 hi/lo, layout [m][h][e] (K-major rows of E).
__device__ __nv_bfloat16 g_WThi[3 * NH * NE];
__device__ __nv_bfloat16 g_WTlo[3 * NH * NE];

__device__ __forceinline__ uint32_t s2u(const void* p) {
    uint32_t a;
    asm("{ .reg .u64 t; cvta.to.shared.u64 t, %1; cvt.u32.u64 %0, t; }"
        : "=r"(a) : "l"(p));
    return a;
}

__device__ __forceinline__ void split2(float v0, float v1, uint32_t& hi, uint32_t& lo) {
    __nv_bfloat16 h0 = __float2bfloat16(v0);
    __nv_bfloat16 h1 = __float2bfloat16(v1);
    __nv_bfloat162 hp = __halves2bfloat162(h0, h1);
    hi = *(uint32_t*)&hp;
    __nv_bfloat162 lp = __halves2bfloat162(
        __float2bfloat16(v0 - __bfloat162float(h0)),
        __float2bfloat16(v1 - __bfloat162float(h1)));
    lo = *(uint32_t*)&lp;
}

// ldmatrix x4: 4 8x8 b16 tiles; lane k supplies row addresses per tile group.
#define LDSM4(r, a)                                                            \
    asm volatile("ldmatrix.sync.aligned.m8n8.x4.shared.b16 {%0,%1,%2,%3}, [%4];" \
        : "=r"((r)[0]), "=r"((r)[1]), "=r"((r)[2]), "=r"((r)[3]) : "r"(a))

#define MMA16816(dd, a, b)                                                     \
    asm volatile("mma.sync.aligned.m16n8k16.row.col.f32.bf16.bf16.f32 "        \
        "{%0,%1,%2,%3}, {%4,%5,%6,%7}, {%8,%9}, {%0,%1,%2,%3};"                \
        : "+f"((dd)[0]), "+f"((dd)[1]), "+f"((dd)[2]), "+f"((dd)[3])           \
        : "r"((a)[0]), "r"((a)[1]), "r"((a)[2]), "r"((a)[3]),                  \
          "r"((b)[0]), "r"((b)[1]))

// ---------------------------------------------------------------------------
// Kernel 0: transpose + bf16-split W -> g_WThi/g_WTlo, layout [m][h][e].
// ---------------------------------------------------------------------------
__global__ void wconv_kernel(const float* __restrict__ Wq,
                             const float* __restrict__ Wk,
                             const float* __restrict__ Wv)
{
    int m = blockIdx.y;
    const float* W = (m == 0) ? Wq : (m == 1 ? Wk : Wv);
    int i = blockIdx.x * 256 + threadIdx.x;   // i = e*64 + h
    int e = i >> 6, h = i & 63;
    float v = W[i];
    __nv_bfloat16 hi = __float2bfloat16(v);
    __nv_bfloat16 lo = __float2bfloat16(v - __bfloat162float(hi));
    int o = (m * NH + h) * NE + e;
    g_WThi[o] = hi;
    g_WTlo[o] = lo;
}

// ---------------------------------------------------------------------------
// Kernel 1: fused QKV projection via mma.sync bf16 (split-2, fp32 accum).
// Grid 128 CTAs x 512 thr. CTA: 128 rows x 192 cols (Q|K|V), K=1024 in 16
// chunks of 64. 16 warps (4m x 4n); warp tile 32 rows x 48 cols = 2 m-frags
// x 6 n-frags of m16n8k16. Products: aH*bH + aH*bL + aL*bH.
// Smem rows are 128B with XOR-16B swizzle: byte = row*128 + (kb ^ ((row&7)<<4)).
// ---------------------------------------------------------------------------
#define QSM_AHI 0
#define QSM_ALO 16384
#define QSM_BHI 32768
#define QSM_BLO 57344
#define QSM_BYTES 81920

__global__ __launch_bounds__(512, 1) void qkv_mma_kernel(const float* __restrict__ x)
{
    extern __shared__ char smem[];
    const uint32_t sb = s2u(smem);
    const int tid  = threadIdx.x;
    const int lane = tid & 31;
    const int wid  = tid >> 5;
    const int wm   = wid & 3;     // 0..3 : 32-row slice
    const int wn   = wid >> 2;    // 0..3 : 48-col slice
    const int row0 = blockIdx.x * 128;

    float d[2][6][4] = {};

    const int xr = tid >> 2;            // 0..127 : x row
    const int xk = (tid & 3) * 16;      // k base within 64-chunk

    #pragma unroll 1
    for (int c = 0; c < 16; ++c) {
        const int k0 = c * 64;
        __syncthreads();  // previous chunk's ldmatrix reads complete

        // x chunk [128 x 64] fp32 -> As hi/lo (bf16, swizzled 128B rows).
        #pragma unroll
        for (int i = 0; i < 4; ++i) {
            int k = xk + i * 4;
            float4 v = *(const float4*)(x + (size_t)(row0 + xr) * NE + k0 + k);
            uint32_t hi01, lo01, hi23, lo23;
            split2(v.x, v.y, hi01, lo01);
            split2(v.z, v.w, hi23, lo23);
            uint32_t off = (uint32_t)(xr * 128) + (uint32_t)((k * 2) ^ ((xr & 7) << 4));
            *(uint2*)(smem + QSM_AHI + off) = make_uint2(hi01, hi23);
            *(uint2*)(smem + QSM_ALO + off) = make_uint2(lo01, lo23);
        }
        // W^T chunk: 192 rows (m*64+h) x 64 k, hi+lo -> Bs.
        #pragma unroll
        for (int i = 0; i < 6; ++i) {
            int lin  = tid + i * 512;          // 0..3071
            int sp   = (lin >= 1536) ? 1 : 0;
            int l2   = lin - sp * 1536;
            int rowb = l2 >> 3;                // 0..191
            int q    = l2 & 7;                 // 16B group
            const __nv_bfloat16* src =
                (sp ? g_WTlo : g_WThi) + ((size_t)rowb * NE + k0 + q * 8);
            uint4 w = *(const uint4*)src;
            uint32_t off = (uint32_t)(rowb * 128) + (uint32_t)((q * 16) ^ ((rowb & 7) << 4));
            *(uint4*)(smem + (sp ? QSM_BLO : QSM_BHI) + off) = w;
        }
        __syncthreads();

        #pragma unroll
        for (int ks = 0; ks < 4; ++ks) {
            const int kb = ks * 32;  // byte offset of this k16 step

            // A fragments (2 m-frags) hi+lo.
            uint32_t aH[2][4], aL[2][4];
            {
                int lr  = lane & 15;
                int lkb = kb + ((lane >> 4) << 4);
                #pragma unroll
                for (int mf = 0; mf < 2; ++mf) {
                    int r = wm * 32 + mf * 16 + lr;
                    uint32_t a = sb + QSM_AHI + r * 128 + (lkb ^ ((r & 7) << 4));
                    LDSM4(aH[mf], a);
                    LDSM4(aL[mf], a + (QSM_ALO - QSM_AHI));
                }
            }
            // B fragments (6 n-frags as 3 x4-loads) hi+lo.
            uint32_t bH[3][4], bL[3][4];
            {
                int nro = (lane & 7) + ((lane >> 4) << 3);
                int lkb = kb + (((lane >> 3) & 1) << 4);
                #pragma unroll
                for (int p = 0; p < 3; ++p) {
                    int r = wn * 48 + p * 16 + nro;
                    uint32_t a = sb + QSM_BHI + r * 128 + (lkb ^ ((r & 7) << 4));
                    LDSM4(bH[p], a);
                    LDSM4(bL[p], a + (QSM_BLO - QSM_BHI));
                }
            }

            #pragma unroll
            for (int mf = 0; mf < 2; ++mf) {
                #pragma unroll
                for (int nf = 0; nf < 6; ++nf) {
                    uint32_t* bh = &bH[nf >> 1][(nf & 1) * 2];
                    uint32_t* bl = &bL[nf >> 1][(nf & 1) * 2];
                    MMA16816(d[mf][nf], aH[mf], bh);
                    MMA16816(d[mf][nf], aH[mf], bl);
                    MMA16816(d[mf][nf], aL[mf], bh);
                }
            }
        }
    }

    // Epilogue: c0/c1 = (row, col), (row, col+1); c2/c3 = row+8.
    const int g = lane >> 2, t = lane & 3;
    #pragma unroll
    for (int mf = 0; mf < 2; ++mf) {
        int r_lo = row0 + wm * 32 + mf * 16 + g;
        #pragma unroll
        for (int nf = 0; nf < 6; ++nf) {
            int col = wn * 48 + nf * 8 + 2 * t;
            int m = col >> 6, h = col & 63;
            float* O = (m == 0) ? g_Q : (m == 1 ? g_K : g_V);
            *(float2*)(O + (size_t)r_lo * NH + h) =
                make_float2(d[mf][nf][0], d[mf][nf][1]);
            *(float2*)(O + (size_t)(r_lo + 8) * NH + h) =
                make_float2(d[mf][nf][2], d[mf][nf][3]);
        }
    }
}

// ---------------------------------------------------------------------------
// Kernel 2: causal flash attention, fp32, online softmax (unchanged, passing).
// ---------------------------------------------------------------------------
__global__ __launch_bounds__(256) void attn_kernel(float* __restrict__ out)
{
    __shared__ float Qs[64 * 64];
    __shared__ float KP[64 * 64];
    __shared__ float Vs[64 * 64];

    const int tid = threadIdx.x;
    const int tx  = tid & 15;
    const int ty  = tid >> 4;
    const int b   = blockIdx.y;

    const float* Qb = g_Q + (size_t)b * NT * NH;
    const float* Kb = g_K + (size_t)b * NT * NH;
    const float* Vb = g_V + (size_t)b * NT * NH;
    float*       Ob = out + (size_t)b * NT * NH;

    const float scale = 0.125f;

    #pragma unroll 1
    for (int qi = 0; qi < 2; ++qi) {
        const int qt   = qi ? (int)blockIdx.x : 31 - (int)blockIdx.x;
        const int row0 = qt * 64;

        __syncthreads();
        #pragma unroll
        for (int it = 0; it < 4; ++it) {
            int idx = tid + it * 256;
            int r   = idx >> 4;
            int h0  = (idx & 15) * 4;
            float4 v = *(const float4*)(Qb + (size_t)(row0 + r) * NH + h0);
            Qs[(h0 + 0) * 64 + (r ^ h0)] = v.x;
            Qs[(h0 + 1) * 64 + (r ^ h0)] = v.y;
            Qs[(h0 + 2) * 64 + (r ^ h0)] = v.z;
            Qs[(h0 + 3) * 64 + (r ^ h0)] = v.w;
        }

        float m[4], l[4], o[4][4];
        #pragma unroll
        for (int i = 0; i < 4; ++i) {
            m[i] = -INFINITY; l[i] = 0.f;
            #pragma unroll
            for (int j = 0; j < 4; ++j) o[i][j] = 0.f;
        }

        #pragma unroll 1
        for (int jt = 0; jt <= qt; ++jt) {
            __syncthreads();
            #pragma unroll
            for (int it = 0; it < 4; ++it) {
                int idx = tid + it * 256;
                int r   = idx >> 4;
                int h0  = (idx & 15) * 4;
                float4 kv = *(const float4*)(Kb + (size_t)(jt * 64 + r) * NH + h0);
                KP[(h0 + 0) * 64 + (r ^ h0)] = kv.x;
                KP[(h0 + 1) * 64 + (r ^ h0)] = kv.y;
                KP[(h0 + 2) * 64 + (r ^ h0)] = kv.z;
                KP[(h0 + 3) * 64 + (r ^ h0)] = kv.w;
                float4 vv = *(const float4*)(Vb + (size_t)(jt * 64 + r) * NH + h0);
                *(float4*)&Vs[r * 64 + h0] = vv;
            }
            __syncthreads();

            float s[4][4] = {};
            #pragma unroll
            for (int h = 0; h < 64; ++h) {
                float4 a  = *(const float4*)&Qs[h * 64 + ((ty * 4) ^ (h & 60))];
                float4 bq = *(const float4*)&KP[h * 64 + ((tx * 4) ^ (h & 60))];
                s[0][0] = fmaf(a.x, bq.x, s[0][0]); s[0][1] = fmaf(a.x, bq.y, s[0][1]);
                s[0][2] = fmaf(a.x, bq.z, s[0][2]); s[0][3] = fmaf(a.x, bq.w, s[0][3]);
                s[1][0] = fmaf(a.y, bq.x, s[1][0]); s[1][1] = fmaf(a.y, bq.y, s[1][1]);
                s[1][2] = fmaf(a.y, bq.z, s[1][2]); s[1][3] = fmaf(a.y, bq.w, s[1][3]);
                s[2][0] = fmaf(a.z, bq.x, s[2][0]); s[2][1] = fmaf(a.z, bq.y, s[2][1]);
                s[2][2] = fmaf(a.z, bq.z, s[2][2]); s[2][3] = fmaf(a.z, bq.w, s[2][3]);
                s[3][0] = fmaf(a.w, bq.x, s[3][0]); s[3][1] = fmaf(a.w, bq.y, s[3][1]);
                s[3][2] = fmaf(a.w, bq.z, s[3][2]); s[3][3] = fmaf(a.w, bq.w, s[3][3]);
            }

            float alpha[4];
            const bool diag = (jt == qt);
            #pragma unroll
            for (int i = 0; i < 4; ++i) {
                const int gi = ty * 4 + i;
                #pragma unroll
                for (int j = 0; j < 4; ++j) {
                    bool masked = diag && ((tx * 4 + j) > gi);
                    s[i][j] = masked ? -INFINITY : s[i][j] * scale;
                }
                float rm = fmaxf(fmaxf(s[i][0], s[i][1]), fmaxf(s[i][2], s[i][3]));
                rm = fmaxf(rm, __shfl_xor_sync(0xffffffffu, rm, 8));
                rm = fmaxf(rm, __shfl_xor_sync(0xffffffffu, rm, 4));
                rm = fmaxf(rm, __shfl_xor_sync(0xffffffffu, rm, 2));
                rm = fmaxf(rm, __shfl_xor_sync(0xffffffffu, rm, 1));
                float nm = fmaxf(m[i], rm);
                float rs = 0.f;
                #pragma unroll
                for (int j = 0; j < 4; ++j) { s[i][j] = __expf(s[i][j] - nm); rs += s[i][j]; }
                rs += __shfl_xor_sync(0xffffffffu, rs, 8);
                rs += __shfl_xor_sync(0xffffffffu, rs, 4);
                rs += __shfl_xor_sync(0xffffffffu, rs, 2);
                rs += __shfl_xor_sync(0xffffffffu, rs, 1);
                alpha[i] = __expf(m[i] - nm);
                l[i] = l[i] * alpha[i] + rs;
                m[i] = nm;
            }

            __syncthreads();
            #pragma unroll
            for (int i = 0; i < 4; ++i) {
                float4 pv = make_float4(s[i][0], s[i][1], s[i][2], s[i][3]);
                *(float4*)&KP[(ty * 4 + i) * 64 + tx * 4] = pv;
            }
            __syncthreads();

            #pragma unroll
            for (int u = 0; u < 4; ++u) {
                o[u][0] *= alpha[u]; o[u][1] *= alpha[u];
                o[u][2] *= alpha[u]; o[u][3] *= alpha[u];
            }
            #pragma unroll
            for (int j4 = 0; j4 < 16; ++j4) {
                float pu[4][4];
                #pragma unroll
                for (int u = 0; u < 4; ++u)
                    *(float4*)pu[u] = *(const float4*)&KP[(ty * 4 + u) * 64 + j4 * 4];
                #pragma unroll
                for (int e = 0; e < 4; ++e) {
                    float4 bv = *(const float4*)&Vs[(j4 * 4 + e) * 64 + tx * 4];
                    #pragma unroll
                    for (int u = 0; u < 4; ++u) {
                        o[u][0] = fmaf(pu[u][e], bv.x, o[u][0]);
                        o[u][1] = fmaf(pu[u][e], bv.y, o[u][1]);
                        o[u][2] = fmaf(pu[u][e], bv.z, o[u][2]);
                        o[u][3] = fmaf(pu[u][e], bv.w, o[u][3]);
                    }
                }
            }
        }

        #pragma unroll
        for (int u = 0; u < 4; ++u) {
            float inv = 1.0f / l[u];
            float4 v = make_float4(o[u][0] * inv, o[u][1] * inv,
                                   o[u][2] * inv, o[u][3] * inv);
            *(float4*)(Ob + (size_t)(row0 + ty * 4 + u) * NH + tx * 4) = v;
        }
    }
}

extern "C" void kernel_launch(void* const* d_in, const int* in_sizes, int n_in,
                              void* d_out, int out_size)
{
    const float* x  = (const float*)d_in[0];
    const float* Wq = (const float*)d_in[1];
    const float* Wk = (const float*)d_in[2];
    const float* Wv = (const float*)d_in[3];
    float* out = (float*)d_out;

    (void)cudaFuncSetAttribute(qkv_mma_kernel,
                               cudaFuncAttributeMaxDynamicSharedMemorySize, QSM_BYTES);

    wconv_kernel<<<dim3(256, 3), 256>>>(Wq, Wk, Wv);
    qkv_mma_kernel<<<128, 512, QSM_BYTES>>>(x);
    attn_kernel<<<dim3(16, 8), 256>>>(out);
}

// round 6
// speedup vs baseline: 2.7143x; 1.6517x over previous
#include <cuda_runtime.h>
#include <cuda_bf16.h>
#include <math.h>
#include <stdint.h>

#define NB 8
#define NT 2048
#define NE 1024
#define NH 64

// Projected Q (pre-scaled by 0.125), K, V as bf16 hi/lo, [B*T][H].
__device__ __nv_bfloat16 g_Qhi[NB * NT * NH];
__device__ __nv_bfloat16 g_Qlo[NB * NT * NH];
__device__ __nv_bfloat16 g_Khi[NB * NT * NH];
__device__ __nv_bfloat16 g_Klo[NB * NT * NH];
__device__ __nv_bfloat16 g_Vhi[NB * NT * NH];
__device__ __nv_bfloat16 g_Vlo[NB * NT * NH];
// W transposed+split to bf16 hi/lo, layout [m][h][e].
__device__ __nv_bfloat16 g_WThi[3 * NH * NE];
__device__ __nv_bfloat16 g_WTlo[3 * NH * NE];

__device__ __forceinline__ uint32_t s2u(const void* p) {
    uint32_t a;
    asm("{ .reg .u64 t; cvta.to.shared.u64 t, %1; cvt.u32.u64 %0, t; }"
        : "=r"(a) : "l"(p));
    return a;
}

__device__ __forceinline__ void split2(float v0, float v1, uint32_t& hi, uint32_t& lo) {
    __nv_bfloat16 h0 = __float2bfloat16(v0);
    __nv_bfloat16 h1 = __float2bfloat16(v1);
    __nv_bfloat162 hp = __halves2bfloat162(h0, h1);
    hi = *(uint32_t*)&hp;
    __nv_bfloat162 lp = __halves2bfloat162(
        __float2bfloat16(v0 - __bfloat162float(h0)),
        __float2bfloat16(v1 - __bfloat162float(h1)));
    lo = *(uint32_t*)&lp;
}

#define LDSM4(r, a)                                                            \
    asm volatile("ldmatrix.sync.aligned.m8n8.x4.shared.b16 {%0,%1,%2,%3}, [%4];" \
        : "=r"((r)[0]), "=r"((r)[1]), "=r"((r)[2]), "=r"((r)[3]) : "r"(a))

#define LDSM4T(r, a)                                                           \
    asm volatile("ldmatrix.sync.aligned.m8n8.x4.trans.shared.b16 {%0,%1,%2,%3}, [%4];" \
        : "=r"((r)[0]), "=r"((r)[1]), "=r"((r)[2]), "=r"((r)[3]) : "r"(a))

#define MMA16816(dd, a, b)                                                     \
    asm volatile("mma.sync.aligned.m16n8k16.row.col.f32.bf16.bf16.f32 "        \
        "{%0,%1,%2,%3}, {%4,%5,%6,%7}, {%8,%9}, {%0,%1,%2,%3};"                \
        : "+f"((dd)[0]), "+f"((dd)[1]), "+f"((dd)[2]), "+f"((dd)[3])           \
        : "r"((a)[0]), "r"((a)[1]), "r"((a)[2]), "r"((a)[3]),                  \
          "r"((b)[0]), "r"((b)[1]))

// ---------------------------------------------------------------------------
// Kernel 0: W -> W^T hi/lo via smem transpose (coalesced 128B row writes).
// Grid (16, 3), 256 threads. Block handles e-slice of 64 for one matrix.
// ---------------------------------------------------------------------------
__global__ __launch_bounds__(256) void wconv_kernel(
    const float* __restrict__ Wq, const float* __restrict__ Wk,
    const float* __restrict__ Wv)
{
    __shared__ float tile[64][65];   // [h][e_local]
    const int m  = blockIdx.y;
    const int e0 = blockIdx.x * 64;
    const float* W = (m == 0) ? Wq : (m == 1 ? Wk : Wv);
    const int tid = threadIdx.x;

    #pragma unroll
    for (int it = 0; it < 4; ++it) {
        int e  = (tid >> 4) + it * 16;
        int h4 = (tid & 15) * 4;
        float4 v = *(const float4*)(W + (size_t)(e0 + e) * NH + h4);
        tile[h4 + 0][e] = v.x; tile[h4 + 1][e] = v.y;
        tile[h4 + 2][e] = v.z; tile[h4 + 3][e] = v.w;
    }
    __syncthreads();

    #pragma unroll
    for (int it = 0; it < 4; ++it) {
        int u   = tid + it * 256;        // 0..1023
        int arr = u >> 9;                // 0=hi 1=lo
        int rem = u & 511;
        int h   = rem >> 3;
        int gp  = rem & 7;
        uint32_t pk[4];
        #pragma unroll
        for (int j = 0; j < 4; ++j) {
            float f0 = tile[h][gp * 8 + 2 * j];
            float f1 = tile[h][gp * 8 + 2 * j + 1];
            uint32_t hi, lo;
            split2(f0, f1, hi, lo);
            pk[j] = arr ? lo : hi;
        }
        __nv_bfloat16* dst = (arr ? g_WTlo : g_WThi) +
                             ((size_t)(m * NH + h) * NE + e0 + gp * 8);
        *(uint4*)dst = make_uint4(pk[0], pk[1], pk[2], pk[3]);
    }
}

// ---------------------------------------------------------------------------
// Kernel 1: fused QKV projection via mma.sync bf16 (split-2, fp32 accum).
// Epilogue emits bf16 hi/lo Q (x0.125), K, V.
// ---------------------------------------------------------------------------
#define QSM_AHI 0
#define QSM_ALO 16384
#define QSM_BHI 32768
#define QSM_BLO 57344
#define QSM_BYTES 81920

__global__ __launch_bounds__(512, 1) void qkv_mma_kernel(const float* __restrict__ x)
{
    extern __shared__ char smem[];
    const uint32_t sb = s2u(smem);
    const int tid  = threadIdx.x;
    const int lane = tid & 31;
    const int wid  = tid >> 5;
    const int wm   = wid & 3;
    const int wn   = wid >> 2;
    const int row0 = blockIdx.x * 128;

    float d[2][6][4] = {};

    const int xr = tid >> 2;
    const int xk = (tid & 3) * 16;

    #pragma unroll 1
    for (int c = 0; c < 16; ++c) {
        const int k0 = c * 64;
        __syncthreads();

        #pragma unroll
        for (int i = 0; i < 4; ++i) {
            int k = xk + i * 4;
            float4 v = *(const float4*)(x + (size_t)(row0 + xr) * NE + k0 + k);
            uint32_t hi01, lo01, hi23, lo23;
            split2(v.x, v.y, hi01, lo01);
            split2(v.z, v.w, hi23, lo23);
            uint32_t off = (uint32_t)(xr * 128) + (uint32_t)((k * 2) ^ ((xr & 7) << 4));
            *(uint2*)(smem + QSM_AHI + off) = make_uint2(hi01, hi23);
            *(uint2*)(smem + QSM_ALO + off) = make_uint2(lo01, lo23);
        }
        #pragma unroll
        for (int i = 0; i < 6; ++i) {
            int lin  = tid + i * 512;
            int sp   = (lin >= 1536) ? 1 : 0;
            int l2   = lin - sp * 1536;
            int rowb = l2 >> 3;
            int q    = l2 & 7;
            const __nv_bfloat16* src =
                (sp ? g_WTlo : g_WThi) + ((size_t)rowb * NE + k0 + q * 8);
            uint4 w = *(const uint4*)src;
            uint32_t off = (uint32_t)(rowb * 128) + (uint32_t)((q * 16) ^ ((rowb & 7) << 4));
            *(uint4*)(smem + (sp ? QSM_BLO : QSM_BHI) + off) = w;
        }
        __syncthreads();

        #pragma unroll
        for (int ks = 0; ks < 4; ++ks) {
            const int kb = ks * 32;
            uint32_t aH[2][4], aL[2][4];
            {
                int lr  = lane & 15;
                int lkb = kb + ((lane >> 4) << 4);
                #pragma unroll
                for (int mf = 0; mf < 2; ++mf) {
                    int r = wm * 32 + mf * 16 + lr;
                    uint32_t a = sb + QSM_AHI + r * 128 + (lkb ^ ((r & 7) << 4));
                    LDSM4(aH[mf], a);
                    LDSM4(aL[mf], a + (QSM_ALO - QSM_AHI));
                }
            }
            uint32_t bH[3][4], bL[3][4];
            {
                int nro = (lane & 7) + ((lane >> 4) << 3);
                int lkb = kb + (((lane >> 3) & 1) << 4);
                #pragma unroll
                for (int p = 0; p < 3; ++p) {
                    int r = wn * 48 + p * 16 + nro;
                    uint32_t a = sb + QSM_BHI + r * 128 + (lkb ^ ((r & 7) << 4));
                    LDSM4(bH[p], a);
                    LDSM4(bL[p], a + (QSM_BLO - QSM_BHI));
                }
            }
            #pragma unroll
            for (int mf = 0; mf < 2; ++mf) {
                #pragma unroll
                for (int nf = 0; nf < 6; ++nf) {
                    uint32_t* bh = &bH[nf >> 1][(nf & 1) * 2];
                    uint32_t* bl = &bL[nf >> 1][(nf & 1) * 2];
                    MMA16816(d[mf][nf], aH[mf], bh);
                    MMA16816(d[mf][nf], aH[mf], bl);
                    MMA16816(d[mf][nf], aL[mf], bh);
                }
            }
        }
    }

    // Epilogue: bf16 hi/lo, Q scaled by 0.125.
    const int g = lane >> 2, t = lane & 3;
    #pragma unroll
    for (int mf = 0; mf < 2; ++mf) {
        int r_lo = row0 + wm * 32 + mf * 16 + g;
        #pragma unroll
        for (int nf = 0; nf < 6; ++nf) {
            int col = wn * 48 + nf * 8 + 2 * t;
            int m = col >> 6, h = col & 63;
            float sc = (m == 0) ? 0.125f : 1.0f;
            __nv_bfloat16* Ohi = (m == 0) ? g_Qhi : (m == 1 ? g_Khi : g_Vhi);
            __nv_bfloat16* Olo = (m == 0) ? g_Qlo : (m == 1 ? g_Klo : g_Vlo);
            uint32_t hi, lo;
            split2(d[mf][nf][0] * sc, d[mf][nf][1] * sc, hi, lo);
            *(uint32_t*)(Ohi + (size_t)r_lo * NH + h) = hi;
            *(uint32_t*)(Olo + (size_t)r_lo * NH + h) = lo;
            split2(d[mf][nf][2] * sc, d[mf][nf][3] * sc, hi, lo);
            *(uint32_t*)(Ohi + (size_t)(r_lo + 8) * NH + h) = hi;
            *(uint32_t*)(Olo + (size_t)(r_lo + 8) * NH + h) = lo;
        }
    }
}

// ---------------------------------------------------------------------------
// Kernel 2: causal flash attention on tensor cores (bf16 split-2).
// Grid (16,8) x 256 thr (8 warps = 4m x 2n). Q-tile 64 rows, paired causal
// schedule (33 key-tile units per CTA). Warp: m16 x n32 for S; PV split by
// k across the two n-warps; O partials combined via smem at q-tile end.
// smem layout (dynamic): Qhi 0, Qlo 8K, Khi 16K, Klo 24K, Vhi 32K, Vlo 40K,
// RED0 48K, RED1 48.5K. O-exchange reuses Khi/Klo (16KB).
// ---------------------------------------------------------------------------
#define ASM_QHI 0
#define ASM_QLO 8192
#define ASM_KV  16384       /* 4 arrays x 8KB: Khi,Klo,Vhi,Vlo */
#define ASM_RED0 49152
#define ASM_RED1 49664
#define ASM_BYTES 50176

__global__ __launch_bounds__(256, 1) void attn_mma_kernel(float* __restrict__ out)
{
    extern __shared__ char sm[];
    const uint32_t sb = s2u(sm);
    float* RED0 = (float*)(sm + ASM_RED0);
    float* RED1 = (float*)(sm + ASM_RED1);

    const int tid  = threadIdx.x;
    const int lane = tid & 31;
    const int wid  = tid >> 5;
    const int wm   = wid & 3;     // m-slice (16 rows)
    const int ns   = wid >> 2;    // n-side (j 0..31 / 32..63)
    const int g    = lane >> 2;
    const int t    = lane & 3;
    const int b    = blockIdx.y;

    const size_t boff = (size_t)b * NT * NH;
    const __nv_bfloat16* kvp[4] = {g_Khi + boff, g_Klo + boff,
                                   g_Vhi + boff, g_Vlo + boff};
    float* Ob = out + boff;

    #pragma unroll 1
    for (int qi = 0; qi < 2; ++qi) {
        const int qt   = qi ? (int)blockIdx.x : 31 - (int)blockIdx.x;
        const int row0 = qt * 64;

        __syncthreads();
        // Load Q tile (hi/lo) into smem.
        #pragma unroll
        for (int it = 0; it < 4; ++it) {
            int u = tid + it * 256;
            int arr = u >> 9, rem = u & 511;
            int r = rem >> 3, gp = rem & 7;
            const __nv_bfloat16* src =
                (arr ? g_Qlo : g_Qhi) + boff + (size_t)(row0 + r) * NH + gp * 8;
            uint4 v = *(const uint4*)src;
            *(uint4*)(sm + (arr ? ASM_QLO : ASM_QHI) + r * 128 +
                      ((gp * 16) ^ ((r & 7) << 4))) = v;
        }

        float Of[8][4] = {};
        float mrow0 = -INFINITY, mrow1 = -INFINITY;
        float lrow0 = 0.f, lrow1 = 0.f;

        // Prefetch tile 0.
        uint4 pf[8];
        #pragma unroll
        for (int it = 0; it < 8; ++it) {
            int u = tid + it * 256;
            int arr = u >> 9, rem = u & 511;
            int r = rem >> 3, gp = rem & 7;
            pf[it] = *(const uint4*)(kvp[arr] + (size_t)r * NH + gp * 8);
        }

        #pragma unroll 1
        for (int jt = 0; jt <= qt; ++jt) {
            __syncthreads();
            #pragma unroll
            for (int it = 0; it < 8; ++it) {
                int u = tid + it * 256;
                int arr = u >> 9, rem = u & 511;
                int r = rem >> 3, gp = rem & 7;
                *(uint4*)(sm + ASM_KV + arr * 8192 + r * 128 +
                          ((gp * 16) ^ ((r & 7) << 4))) = pf[it];
            }
            __syncthreads();
            if (jt < qt) {
                #pragma unroll
                for (int it = 0; it < 8; ++it) {
                    int u = tid + it * 256;
                    int arr = u >> 9, rem = u & 511;
                    int r = rem >> 3, gp = rem & 7;
                    pf[it] = *(const uint4*)(kvp[arr] +
                              (size_t)((jt + 1) * 64 + r) * NH + gp * 8);
                }
            }

            // ---- S = Q K^T (3 split products) ----
            float S[4][4] = {};
            #pragma unroll
            for (int kf = 0; kf < 4; ++kf) {
                const int kb = kf * 32;
                uint32_t aH[4], aL[4];
                {
                    int r = wm * 16 + (lane & 15);
                    int lkb = kb + ((lane >> 4) << 4);
                    uint32_t a = sb + ASM_QHI + r * 128 + (lkb ^ ((r & 7) << 4));
                    LDSM4(aH, a);
                    LDSM4(aL, a + 8192);
                }
                uint32_t bKH[2][4], bKL[2][4];
                {
                    int nro = (lane & 7) + ((lane >> 4) << 3);
                    int lkb = kb + (((lane >> 3) & 1) << 4);
                    #pragma unroll
                    for (int p = 0; p < 2; ++p) {
                        int r = ns * 32 + p * 16 + nro;
                        uint32_t a = sb + ASM_KV + r * 128 + (lkb ^ ((r & 7) << 4));
                        LDSM4(bKH[p], a);
                        LDSM4(bKL[p], a + 8192);
                    }
                }
                #pragma unroll
                for (int nf = 0; nf < 4; ++nf) {
                    uint32_t* bh = &bKH[nf >> 1][(nf & 1) * 2];
                    uint32_t* bl = &bKL[nf >> 1][(nf & 1) * 2];
                    MMA16816(S[nf], aH, bh);
                    MMA16816(S[nf], aH, bl);
                    MMA16816(S[nf], aL, bh);
                }
            }

            // ---- mask + online softmax ----
            if (jt == qt) {
                #pragma unroll
                for (int nf = 0; nf < 4; ++nf) {
                    int col = ns * 32 + nf * 8 + 2 * t;
                    int r0r = wm * 16 + g;
                    if (col     > r0r)     S[nf][0] = -INFINITY;
                    if (col + 1 > r0r)     S[nf][1] = -INFINITY;
                    if (col     > r0r + 8) S[nf][2] = -INFINITY;
                    if (col + 1 > r0r + 8) S[nf][3] = -INFINITY;
                }
            }
            float mx0 = -INFINITY, mx1 = -INFINITY;
            #pragma unroll
            for (int nf = 0; nf < 4; ++nf) {
                mx0 = fmaxf(mx0, fmaxf(S[nf][0], S[nf][1]));
                mx1 = fmaxf(mx1, fmaxf(S[nf][2], S[nf][3]));
            }
            mx0 = fmaxf(mx0, __shfl_xor_sync(0xffffffffu, mx0, 1));
            mx0 = fmaxf(mx0, __shfl_xor_sync(0xffffffffu, mx0, 2));
            mx1 = fmaxf(mx1, __shfl_xor_sync(0xffffffffu, mx1, 1));
            mx1 = fmaxf(mx1, __shfl_xor_sync(0xffffffffu, mx1, 2));
            if (t == 0) {
                RED0[(wm * 2 + ns) * 16 + g]     = mx0;
                RED0[(wm * 2 + ns) * 16 + g + 8] = mx1;
            }
            __syncthreads();
            mx0 = fmaxf(mx0, RED0[(wm * 2 + (1 - ns)) * 16 + g]);
            mx1 = fmaxf(mx1, RED0[(wm * 2 + (1 - ns)) * 16 + g + 8]);
            float nm0 = fmaxf(mrow0, mx0);
            float nm1 = fmaxf(mrow1, mx1);

            float s0 = 0.f, s1 = 0.f;
            #pragma unroll
            for (int nf = 0; nf < 4; ++nf) {
                S[nf][0] = __expf(S[nf][0] - nm0); s0 += S[nf][0];
                S[nf][1] = __expf(S[nf][1] - nm0); s0 += S[nf][1];
                S[nf][2] = __expf(S[nf][2] - nm1); s1 += S[nf][2];
                S[nf][3] = __expf(S[nf][3] - nm1); s1 += S[nf][3];
            }
            s0 += __shfl_xor_sync(0xffffffffu, s0, 1);
            s0 += __shfl_xor_sync(0xffffffffu, s0, 2);
            s1 += __shfl_xor_sync(0xffffffffu, s1, 1);
            s1 += __shfl_xor_sync(0xffffffffu, s1, 2);
            if (t == 0) {
                RED1[(wm * 2 + ns) * 16 + g]     = s0;
                RED1[(wm * 2 + ns) * 16 + g + 8] = s1;
            }
            __syncthreads();
            s0 += RED1[(wm * 2 + (1 - ns)) * 16 + g];
            s1 += RED1[(wm * 2 + (1 - ns)) * 16 + g + 8];

            float al0 = __expf(mrow0 - nm0);
            float al1 = __expf(mrow1 - nm1);
            lrow0 = lrow0 * al0 + s0;
            lrow1 = lrow1 * al1 + s1;
            mrow0 = nm0; mrow1 = nm1;

            #pragma unroll
            for (int hf = 0; hf < 8; ++hf) {
                Of[hf][0] *= al0; Of[hf][1] *= al0;
                Of[hf][2] *= al1; Of[hf][3] *= al1;
            }

            // ---- pack P (hi/lo) into A-fragments, register-only ----
            uint32_t pH[2][4], pL[2][4];
            #pragma unroll
            for (int kk = 0; kk < 2; ++kk) {
                split2(S[2 * kk][0],     S[2 * kk][1],     pH[kk][0], pL[kk][0]);
                split2(S[2 * kk][2],     S[2 * kk][3],     pH[kk][1], pL[kk][1]);
                split2(S[2 * kk + 1][0], S[2 * kk + 1][1], pH[kk][2], pL[kk][2]);
                split2(S[2 * kk + 1][2], S[2 * kk + 1][3], pH[kk][3], pL[kk][3]);
            }

            // ---- O += P V (this warp's k32 slice; V frags via ldmatrix.trans)
            #pragma unroll
            for (int kk = 0; kk < 2; ++kk) {
                int jrow = ns * 32 + kk * 16 + (lane & 7) + ((lane >> 3) & 1) * 8;
                #pragma unroll
                for (int hp = 0; hp < 4; ++hp) {
                    int hbyte = hp * 32 + ((lane >> 4) << 4);
                    uint32_t a = sb + ASM_KV + 16384 + jrow * 128 +
                                 (hbyte ^ ((jrow & 7) << 4));
                    uint32_t vH[4], vL[4];
                    LDSM4T(vH, a);
                    LDSM4T(vL, a + 8192);
                    #pragma unroll
                    for (int e = 0; e < 2; ++e) {
                        int hf = 2 * hp + e;
                        uint32_t* bh = &vH[e * 2];
                        uint32_t* bl = &vL[e * 2];
                        MMA16816(Of[hf], pH[kk], bh);
                        MMA16816(Of[hf], pH[kk], bl);
                        MMA16816(Of[hf], pL[kk], bh);
                    }
                }
            }
        }

        // ---- combine n-side partials, normalize, store ----
        __syncthreads();
        if (ns == 1) {
            float* Oex = (float*)(sm + ASM_KV);
            #pragma unroll
            for (int hf = 0; hf < 8; ++hf)
                *(float4*)&Oex[((wm * 32 + lane) * 32) + hf * 4] =
                    make_float4(Of[hf][0], Of[hf][1], Of[hf][2], Of[hf][3]);
        }
        __syncthreads();
        if (ns == 0) {
            const float* Oex = (const float*)(sm + ASM_KV);
            float inv0 = 1.0f / lrow0;
            float inv1 = 1.0f / lrow1;
            int r_g  = row0 + wm * 16 + g;
            #pragma unroll
            for (int hf = 0; hf < 8; ++hf) {
                float4 ox = *(const float4*)&Oex[((wm * 32 + lane) * 32) + hf * 4];
                int h = hf * 8 + 2 * t;
                *(float2*)(Ob + (size_t)r_g * NH + h) =
                    make_float2((Of[hf][0] + ox.x) * inv0, (Of[hf][1] + ox.y) * inv0);
                *(float2*)(Ob + (size_t)(r_g + 8) * NH + h) =
                    make_float2((Of[hf][2] + ox.z) * inv1, (Of[hf][3] + ox.w) * inv1);
            }
        }
    }
}

extern "C" void kernel_launch(void* const* d_in, const int* in_sizes, int n_in,
                              void* d_out, int out_size)
{
    const float* x  = (const float*)d_in[0];
    const float* Wq = (const float*)d_in[1];
    const float* Wk = (const float*)d_in[2];
    const float* Wv = (const float*)d_in[3];
    float* out = (float*)d_out;

    (void)cudaFuncSetAttribute(qkv_mma_kernel,
                               cudaFuncAttributeMaxDynamicSharedMemorySize, QSM_BYTES);
    (void)cudaFuncSetAttribute(attn_mma_kernel,
                               cudaFuncAttributeMaxDynamicSharedMemorySize, ASM_BYTES);

    wconv_kernel<<<dim3(16, 3), 256>>>(Wq, Wk, Wv);
    qkv_mma_kernel<<<128, 512, QSM_BYTES>>>(x);
    attn_mma_kernel<<<dim3(16, 8), 256, ASM_BYTES>>>(out);
}

// round 8
// speedup vs baseline: 2.8671x; 1.0563x over previous
#include <cuda_runtime.h>
#include <cuda_bf16.h>
#include <math.h>
#include <stdint.h>

#define NB 8
#define NT 2048
#define NE 1024
#define NH 64

// Projected Q (pre-scaled by 0.125), K, V as bf16 hi/lo, [B*T][H].
__device__ __nv_bfloat16 g_Qhi[NB * NT * NH];
__device__ __nv_bfloat16 g_Qlo[NB * NT * NH];
__device__ __nv_bfloat16 g_Khi[NB * NT * NH];
__device__ __nv_bfloat16 g_Klo[NB * NT * NH];
__device__ __nv_bfloat16 g_Vhi[NB * NT * NH];
__device__ __nv_bfloat16 g_Vlo[NB * NT * NH];
// W transposed+split to bf16 hi/lo, layout [m][h][e].
__device__ __nv_bfloat16 g_WThi[3 * NH * NE];
__device__ __nv_bfloat16 g_WTlo[3 * NH * NE];

__device__ __forceinline__ uint32_t s2u(const void* p) {
    uint32_t a;
    asm("{ .reg .u64 t; cvta.to.shared.u64 t, %1; cvt.u32.u64 %0, t; }"
        : "=r"(a) : "l"(p));
    return a;
}

__device__ __forceinline__ void split2(float v0, float v1, uint32_t& hi, uint32_t& lo) {
    __nv_bfloat16 h0 = __float2bfloat16(v0);
    __nv_bfloat16 h1 = __float2bfloat16(v1);
    __nv_bfloat162 hp = __halves2bfloat162(h0, h1);
    hi = *(uint32_t*)&hp;
    __nv_bfloat162 lp = __halves2bfloat162(
        __float2bfloat16(v0 - __bfloat162float(h0)),
        __float2bfloat16(v1 - __bfloat162float(h1)));
    lo = *(uint32_t*)&lp;
}

#define LDSM4(r, a)                                                            \
    asm volatile("ldmatrix.sync.aligned.m8n8.x4.shared.b16 {%0,%1,%2,%3}, [%4];" \
        : "=r"((r)[0]), "=r"((r)[1]), "=r"((r)[2]), "=r"((r)[3]) : "r"(a))

#define LDSM4T(r, a)                                                           \
    asm volatile("ldmatrix.sync.aligned.m8n8.x4.trans.shared.b16 {%0,%1,%2,%3}, [%4];" \
        : "=r"((r)[0]), "=r"((r)[1]), "=r"((r)[2]), "=r"((r)[3]) : "r"(a))

#define MMA16816(dd, a, b)                                                     \
    asm volatile("mma.sync.aligned.m16n8k16.row.col.f32.bf16.bf16.f32 "        \
        "{%0,%1,%2,%3}, {%4,%5,%6,%7}, {%8,%9}, {%0,%1,%2,%3};"                \
        : "+f"((dd)[0]), "+f"((dd)[1]), "+f"((dd)[2]), "+f"((dd)[3])           \
        : "r"((a)[0]), "r"((a)[1]), "r"((a)[2]), "r"((a)[3]),                  \
          "r"((b)[0]), "r"((b)[1]))

// ---------------------------------------------------------------------------
// Kernel 0: W -> W^T hi/lo via smem transpose (coalesced 128B row writes).
// ---------------------------------------------------------------------------
__global__ __launch_bounds__(256) void wconv_kernel(
    const float* __restrict__ Wq, const float* __restrict__ Wk,
    const float* __restrict__ Wv)
{
    __shared__ float tile[64][65];
    const int m  = blockIdx.y;
    const int e0 = blockIdx.x * 64;
    const float* W = (m == 0) ? Wq : (m == 1 ? Wk : Wv);
    const int tid = threadIdx.x;

    #pragma unroll
    for (int it = 0; it < 4; ++it) {
        int e  = (tid >> 4) + it * 16;
        int h4 = (tid & 15) * 4;
        float4 v = *(const float4*)(W + (size_t)(e0 + e) * NH + h4);
        tile[h4 + 0][e] = v.x; tile[h4 + 1][e] = v.y;
        tile[h4 + 2][e] = v.z; tile[h4 + 3][e] = v.w;
    }
    __syncthreads();

    #pragma unroll
    for (int it = 0; it < 4; ++it) {
        int u   = tid + it * 256;
        int arr = u >> 9;
        int rem = u & 511;
        int h   = rem >> 3;
        int gp  = rem & 7;
        uint32_t pk[4];
        #pragma unroll
        for (int j = 0; j < 4; ++j) {
            float f0 = tile[h][gp * 8 + 2 * j];
            float f1 = tile[h][gp * 8 + 2 * j + 1];
            uint32_t hi, lo;
            split2(f0, f1, hi, lo);
            pk[j] = arr ? lo : hi;
        }
        __nv_bfloat16* dst = (arr ? g_WTlo : g_WThi) +
                             ((size_t)(m * NH + h) * NE + e0 + gp * 8);
        *(uint4*)dst = make_uint4(pk[0], pk[1], pk[2], pk[3]);
    }
}

// ---------------------------------------------------------------------------
// Kernel 1: fused QKV projection via mma.sync bf16 (split-2, fp32 accum).
// ---------------------------------------------------------------------------
#define QSM_AHI 0
#define QSM_ALO 16384
#define QSM_BHI 32768
#define QSM_BLO 57344
#define QSM_BYTES 81920

__global__ __launch_bounds__(512, 1) void qkv_mma_kernel(const float* __restrict__ x)
{
    extern __shared__ char smem[];
    const uint32_t sb = s2u(smem);
    const int tid  = threadIdx.x;
    const int lane = tid & 31;
    const int wid  = tid >> 5;
    const int wm   = wid & 3;
    const int wn   = wid >> 2;
    const int row0 = blockIdx.x * 128;

    float d[2][6][4] = {};

    const int xr = tid >> 2;
    const int xk = (tid & 3) * 16;

    #pragma unroll 1
    for (int c = 0; c < 16; ++c) {
        const int k0 = c * 64;
        __syncthreads();

        #pragma unroll
        for (int i = 0; i < 4; ++i) {
            int k = xk + i * 4;
            float4 v = *(const float4*)(x + (size_t)(row0 + xr) * NE + k0 + k);
            uint32_t hi01, lo01, hi23, lo23;
            split2(v.x, v.y, hi01, lo01);
            split2(v.z, v.w, hi23, lo23);
            uint32_t off = (uint32_t)(xr * 128) + (uint32_t)((k * 2) ^ ((xr & 7) << 4));
            *(uint2*)(smem + QSM_AHI + off) = make_uint2(hi01, hi23);
            *(uint2*)(smem + QSM_ALO + off) = make_uint2(lo01, lo23);
        }
        #pragma unroll
        for (int i = 0; i < 6; ++i) {
            int lin  = tid + i * 512;
            int sp   = (lin >= 1536) ? 1 : 0;
            int l2   = lin - sp * 1536;
            int rowb = l2 >> 3;
            int q    = l2 & 7;
            const __nv_bfloat16* src =
                (sp ? g_WTlo : g_WThi) + ((size_t)rowb * NE + k0 + q * 8);
            uint4 w = *(const uint4*)src;
            uint32_t off = (uint32_t)(rowb * 128) + (uint32_t)((q * 16) ^ ((rowb & 7) << 4));
            *(uint4*)(smem + (sp ? QSM_BLO : QSM_BHI) + off) = w;
        }
        __syncthreads();

        #pragma unroll
        for (int ks = 0; ks < 4; ++ks) {
            const int kb = ks * 32;
            uint32_t aH[2][4], aL[2][4];
            {
                int lr  = lane & 15;
                int lkb = kb + ((lane >> 4) << 4);
                #pragma unroll
                for (int mf = 0; mf < 2; ++mf) {
                    int r = wm * 32 + mf * 16 + lr;
                    uint32_t a = sb + QSM_AHI + r * 128 + (lkb ^ ((r & 7) << 4));
                    LDSM4(aH[mf], a);
                    LDSM4(aL[mf], a + (QSM_ALO - QSM_AHI));
                }
            }
            uint32_t bH[3][4], bL[3][4];
            {
                int nro = (lane & 7) + ((lane >> 4) << 3);
                int lkb = kb + (((lane >> 3) & 1) << 4);
                #pragma unroll
                for (int p = 0; p < 3; ++p) {
                    int r = wn * 48 + p * 16 + nro;
                    uint32_t a = sb + QSM_BHI + r * 128 + (lkb ^ ((r & 7) << 4));
                    LDSM4(bH[p], a);
                    LDSM4(bL[p], a + (QSM_BLO - QSM_BHI));
                }
            }
            #pragma unroll
            for (int mf = 0; mf < 2; ++mf) {
                #pragma unroll
                for (int nf = 0; nf < 6; ++nf) {
                    uint32_t* bh = &bH[nf >> 1][(nf & 1) * 2];
                    uint32_t* bl = &bL[nf >> 1][(nf & 1) * 2];
                    MMA16816(d[mf][nf], aH[mf], bh);
                    MMA16816(d[mf][nf], aH[mf], bl);
                    MMA16816(d[mf][nf], aL[mf], bh);
                }
            }
        }
    }

    const int g = lane >> 2, t = lane & 3;
    #pragma unroll
    for (int mf = 0; mf < 2; ++mf) {
        int r_lo = row0 + wm * 32 + mf * 16 + g;
        #pragma unroll
        for (int nf = 0; nf < 6; ++nf) {
            int col = wn * 48 + nf * 8 + 2 * t;
            int m = col >> 6, h = col & 63;
            float sc = (m == 0) ? 0.125f : 1.0f;
            __nv_bfloat16* Ohi = (m == 0) ? g_Qhi : (m == 1 ? g_Khi : g_Vhi);
            __nv_bfloat16* Olo = (m == 0) ? g_Qlo : (m == 1 ? g_Klo : g_Vlo);
            uint32_t hi, lo;
            split2(d[mf][nf][0] * sc, d[mf][nf][1] * sc, hi, lo);
            *(uint32_t*)(Ohi + (size_t)r_lo * NH + h) = hi;
            *(uint32_t*)(Olo + (size_t)r_lo * NH + h) = lo;
            split2(d[mf][nf][2] * sc, d[mf][nf][3] * sc, hi, lo);
            *(uint32_t*)(Ohi + (size_t)(r_lo + 8) * NH + h) = hi;
            *(uint32_t*)(Olo + (size_t)(r_lo + 8) * NH + h) = lo;
        }
    }
}

// ---------------------------------------------------------------------------
// Kernel 2: causal flash attention, tensor cores, per-warp-local softmax,
// double-buffered KV smem (ONE barrier per key tile).
// Each n-warp owns a 32-key-column subset and a private (m,l,O); the two
// sides merge once per q-tile. Mask value is finite (-1e30): dead subsets
// get merge weight exp(-1e30 - M) == 0, so no NaN paths.
// smem: Qhi 0, Qlo 8K, KVbuf0 16K(32K), KVbuf1 48K(32K), REDm 80K, REDl 80.5K.
// O-exchange aliases KVbuf0.
// ---------------------------------------------------------------------------
#define ASM_QHI  0
#define ASM_QLO  8192
#define ASM_KV0  16384
#define ASM_KV1  49152
#define ASM_REDM 81920
#define ASM_REDL 82432
#define ASM_BYTES 82944
#define MASKV (-1e30f)

__global__ __launch_bounds__(256, 1) void attn_mma_kernel(float* __restrict__ out)
{
    extern __shared__ char sm[];
    const uint32_t sb = s2u(sm);
    float* REDm = (float*)(sm + ASM_REDM);
    float* REDl = (float*)(sm + ASM_REDL);

    const int tid  = threadIdx.x;
    const int lane = tid & 31;
    const int wid  = tid >> 5;
    const int wm   = wid & 3;     // m-slice (16 rows)
    const int ns   = wid >> 2;    // n-side (key cols 0..31 / 32..63)
    const int g    = lane >> 2;
    const int t    = lane & 3;
    const int b    = blockIdx.y;

    const size_t boff = (size_t)b * NT * NH;
    const __nv_bfloat16* kvp[4] = {g_Khi + boff, g_Klo + boff,
                                   g_Vhi + boff, g_Vlo + boff};
    float* Ob = out + boff;

    #pragma unroll 1
    for (int qi = 0; qi < 2; ++qi) {
        const int qt   = qi ? (int)blockIdx.x : 31 - (int)blockIdx.x;
        const int row0 = qt * 64;

        __syncthreads();  // all smem consumers of previous q-tile done
        // Q tile (hi/lo) -> smem.
        #pragma unroll
        for (int it = 0; it < 4; ++it) {
            int u = tid + it * 256;
            int arr = u >> 9, rem = u & 511;
            int r = rem >> 3, gp = rem & 7;
            const __nv_bfloat16* src =
                (arr ? g_Qlo : g_Qhi) + boff + (size_t)(row0 + r) * NH + gp * 8;
            uint4 v = *(const uint4*)src;
            *(uint4*)(sm + (arr ? ASM_QLO : ASM_QHI) + r * 128 +
                      ((gp * 16) ^ ((r & 7) << 4))) = v;
        }

        float Of[8][4] = {};
        float mrow0 = MASKV, mrow1 = MASKV;
        float lrow0 = 0.f, lrow1 = 0.f;

        // Tile 0 -> buf0.
        uint4 pf[8];
        #pragma unroll
        for (int it = 0; it < 8; ++it) {
            int u = tid + it * 256;
            int arr = u >> 9, rem = u & 511;
            int r = rem >> 3, gp = rem & 7;
            pf[it] = *(const uint4*)(kvp[arr] + (size_t)r * NH + gp * 8);
        }
        #pragma unroll
        for (int it = 0; it < 8; ++it) {
            int u = tid + it * 256;
            int arr = u >> 9, rem = u & 511;
            int r = rem >> 3, gp = rem & 7;
            *(uint4*)(sm + ASM_KV0 + arr * 8192 + r * 128 +
                      ((gp * 16) ^ ((r & 7) << 4))) = pf[it];
        }
        __syncthreads();  // Q + buf0 ready

        #pragma unroll 1
        for (int jt = 0; jt <= qt; ++jt) {
            const uint32_t ub = sb + ((jt & 1) ? ASM_KV1 : ASM_KV0);

            // Prefetch next tile (overlaps compute).
            if (jt < qt) {
                #pragma unroll
                for (int it = 0; it < 8; ++it) {
                    int u = tid + it * 256;
                    int arr = u >> 9, rem = u & 511;
                    int r = rem >> 3, gp = rem & 7;
                    pf[it] = *(const uint4*)(kvp[arr] +
                              (size_t)((jt + 1) * 64 + r) * NH + gp * 8);
                }
            }

            // ---- S = Q K^T (3 split products) ----
            float S[4][4] = {};
            #pragma unroll
            for (int kf = 0; kf < 4; ++kf) {
                const int kb = kf * 32;
                uint32_t aH[4], aL[4];
                {
                    int r = wm * 16 + (lane & 15);
                    int lkb = kb + ((lane >> 4) << 4);
                    uint32_t a = sb + ASM_QHI + r * 128 + (lkb ^ ((r & 7) << 4));
                    LDSM4(aH, a);
                    LDSM4(aL, a + 8192);
                }
                uint32_t bKH[2][4], bKL[2][4];
                {
                    int nro = (lane & 7) + ((lane >> 4) << 3);
                    int lkb = kb + (((lane >> 3) & 1) << 4);
                    #pragma unroll
                    for (int p = 0; p < 2; ++p) {
                        int r = ns * 32 + p * 16 + nro;
                        uint32_t a = ub + r * 128 + (lkb ^ ((r & 7) << 4));
                        LDSM4(bKH[p], a);
                        LDSM4(bKL[p], a + 8192);
                    }
                }
                #pragma unroll
                for (int nf = 0; nf < 4; ++nf) {
                    uint32_t* bh = &bKH[nf >> 1][(nf & 1) * 2];
                    uint32_t* bl = &bKL[nf >> 1][(nf & 1) * 2];
                    MMA16816(S[nf], aH, bh);
                    MMA16816(S[nf], aH, bl);
                    MMA16816(S[nf], aL, bh);
                }
            }

            // ---- mask + per-warp online softmax (no cross-warp traffic) ----
            if (jt == qt) {
                #pragma unroll
                for (int nf = 0; nf < 4; ++nf) {
                    int col = ns * 32 + nf * 8 + 2 * t;
                    int r0r = wm * 16 + g;
                    if (col     > r0r)     S[nf][0] = MASKV;
                    if (col + 1 > r0r)     S[nf][1] = MASKV;
                    if (col     > r0r + 8) S[nf][2] = MASKV;
                    if (col + 1 > r0r + 8) S[nf][3] = MASKV;
                }
            }
            float mx0 = MASKV, mx1 = MASKV;
            #pragma unroll
            for (int nf = 0; nf < 4; ++nf) {
                mx0 = fmaxf(mx0, fmaxf(S[nf][0], S[nf][1]));
                mx1 = fmaxf(mx1, fmaxf(S[nf][2], S[nf][3]));
            }
            mx0 = fmaxf(mx0, __shfl_xor_sync(0xffffffffu, mx0, 1));
            mx0 = fmaxf(mx0, __shfl_xor_sync(0xffffffffu, mx0, 2));
            mx1 = fmaxf(mx1, __shfl_xor_sync(0xffffffffu, mx1, 1));
            mx1 = fmaxf(mx1, __shfl_xor_sync(0xffffffffu, mx1, 2));
            float nm0 = fmaxf(mrow0, mx0);
            float nm1 = fmaxf(mrow1, mx1);

            float s0 = 0.f, s1 = 0.f;
            #pragma unroll
            for (int nf = 0; nf < 4; ++nf) {
                S[nf][0] = __expf(S[nf][0] - nm0); s0 += S[nf][0];
                S[nf][1] = __expf(S[nf][1] - nm0); s0 += S[nf][1];
                S[nf][2] = __expf(S[nf][2] - nm1); s1 += S[nf][2];
                S[nf][3] = __expf(S[nf][3] - nm1); s1 += S[nf][3];
            }
            s0 += __shfl_xor_sync(0xffffffffu, s0, 1);
            s0 += __shfl_xor_sync(0xffffffffu, s0, 2);
            s1 += __shfl_xor_sync(0xffffffffu, s1, 1);
            s1 += __shfl_xor_sync(0xffffffffu, s1, 2);

            float al0 = __expf(mrow0 - nm0);
            float al1 = __expf(mrow1 - nm1);
            lrow0 = lrow0 * al0 + s0;
            lrow1 = lrow1 * al1 + s1;
            mrow0 = nm0; mrow1 = nm1;

            #pragma unroll
            for (int hf = 0; hf < 8; ++hf) {
                Of[hf][0] *= al0; Of[hf][1] *= al0;
                Of[hf][2] *= al1; Of[hf][3] *= al1;
            }

            // ---- pack P into A-fragments (register-only) ----
            uint32_t pH[2][4], pL[2][4];
            #pragma unroll
            for (int kk = 0; kk < 2; ++kk) {
                split2(S[2 * kk][0],     S[2 * kk][1],     pH[kk][0], pL[kk][0]);
                split2(S[2 * kk][2],     S[2 * kk][3],     pH[kk][1], pL[kk][1]);
                split2(S[2 * kk + 1][0], S[2 * kk + 1][1], pH[kk][2], pL[kk][2]);
                split2(S[2 * kk + 1][2], S[2 * kk + 1][3], pH[kk][3], pL[kk][3]);
            }

            // ---- O += P V over this warp's 32 keys ----
            #pragma unroll
            for (int kk = 0; kk < 2; ++kk) {
                int jrow = ns * 32 + kk * 16 + (lane & 7) + ((lane >> 3) & 1) * 8;
                #pragma unroll
                for (int hp = 0; hp < 4; ++hp) {
                    int hbyte = hp * 32 + ((lane >> 4) << 4);
                    uint32_t a = ub + 16384 + jrow * 128 +
                                 (hbyte ^ ((jrow & 7) << 4));
                    uint32_t vH[4], vL[4];
                    LDSM4T(vH, a);
                    LDSM4T(vL, a + 8192);
                    #pragma unroll
                    for (int e = 0; e < 2; ++e) {
                        int hf = 2 * hp + e;
                        uint32_t* bh = &vH[e * 2];
                        uint32_t* bl = &vL[e * 2];
                        MMA16816(Of[hf], pH[kk], bh);
                        MMA16816(Of[hf], pH[kk], bl);
                        MMA16816(Of[hf], pL[kk], bh);
                    }
                }
            }

            // ---- publish next tile (single barrier per iteration) ----
            if (jt < qt) {
                char* nb = sm + ((jt & 1) ? ASM_KV0 : ASM_KV1);
                #pragma unroll
                for (int it = 0; it < 8; ++it) {
                    int u = tid + it * 256;
                    int arr = u >> 9, rem = u & 511;
                    int r = rem >> 3, gp = rem & 7;
                    *(uint4*)(nb + arr * 8192 + r * 128 +
                              ((gp * 16) ^ ((r & 7) << 4))) = pf[it];
                }
                __syncthreads();
            }
        }

        // ---- merge the two n-side accumulators, normalize, store ----
        __syncthreads();  // all compute (incl. reads of KV0) done
        if (t == 0) {
            REDm[(wm * 2 + ns) * 16 + g]     = mrow0;
            REDm[(wm * 2 + ns) * 16 + 8 + g] = mrow1;
        }
        __syncthreads();
        float om0 = REDm[(wm * 2 + (1 - ns)) * 16 + g];
        float om1 = REDm[(wm * 2 + (1 - ns)) * 16 + 8 + g];
        float M0 = fmaxf(mrow0, om0), M1 = fmaxf(mrow1, om1);
        float w0 = __expf(mrow0 - M0), w1 = __expf(mrow1 - M1);
        lrow0 *= w0; lrow1 *= w1;
        #pragma unroll
        for (int hf = 0; hf < 8; ++hf) {
            Of[hf][0] *= w0; Of[hf][1] *= w0;
            Of[hf][2] *= w1; Of[hf][3] *= w1;
        }
        if (ns == 1) {
            float* Oex = (float*)(sm + ASM_KV0);
            #pragma unroll
            for (int hf = 0; hf < 8; ++hf)
                *(float4*)&Oex[((wm * 32 + lane) * 32) + hf * 4] =
                    make_float4(Of[hf][0], Of[hf][1], Of[hf][2], Of[hf][3]);
            if (t == 0) {
                REDl[wm * 16 + g]     = lrow0;
                REDl[wm * 16 + 8 + g] = lrow1;
            }
        }
        __syncthreads();
        if (ns == 0) {
            const float* Oex = (const float*)(sm + ASM_KV0);
            float lt0 = lrow0 + REDl[wm * 16 + g];
            float lt1 = lrow1 + REDl[wm * 16 + 8 + g];
            float inv0 = 1.0f / lt0;
            float inv1 = 1.0f / lt1;
            int r_g = row0 + wm * 16 + g;
            #pragma unroll
            for (int hf = 0; hf < 8; ++hf) {
                float4 ox = *(const float4*)&Oex[((wm * 32 + lane) * 32) + hf * 4];
                int h = hf * 8 + 2 * t;
                *(float2*)(Ob + (size_t)r_g * NH + h) =
                    make_float2((Of[hf][0] + ox.x) * inv0, (Of[hf][1] + ox.y) * inv0);
                *(float2*)(Ob + (size_t)(r_g + 8) * NH + h) =
                    make_float2((Of[hf][2] + ox.z) * inv1, (Of[hf][3] + ox.w) * inv1);
            }
        }
    }
}

extern "C" void kernel_launch(void* const* d_in, const int* in_sizes, int n_in,
                              void* d_out, int out_size)
{
    const float* x  = (const float*)d_in[0];
    const float* Wq = (const float*)d_in[1];
    const float* Wk = (const float*)d_in[2];
    const float* Wv = (const float*)d_in[3];
    float* out = (float*)d_out;

    (void)cudaFuncSetAttribute(qkv_mma_kernel,
                               cudaFuncAttributeMaxDynamicSharedMemorySize, QSM_BYTES);
    (void)cudaFuncSetAttribute(attn_mma_kernel,
                               cudaFuncAttributeMaxDynamicSharedMemorySize, ASM_BYTES);

    wconv_kernel<<<dim3(16, 3), 256>>>(Wq, Wk, Wv);
    qkv_mma_kernel<<<128, 512, QSM_BYTES>>>(x);
    attn_mma_kernel<<<dim3(16, 8), 256, ASM_BYTES>>>(out);
}